// round 15
// baseline (speedup 1.0000x reference)
#include <cuda_runtime.h>
#include <cuda_fp16.h>
#include <math.h>
#include <stdint.h>

#define B 8192
#define D 256
#define P 4096
#define MASKW 256                      /* B/32 mask words per row */
#define LDC 72                         /* chunk smem stride in halves (64+8) */
#define CHUNK_BYTES (128*LDC*2)        /* 18432 per matrix per stage */
#define STAGE_BYTES (2*CHUNK_BYTES)    /* A+B: 36864 */
#define GEMM_SMEM   (2*STAGE_BYTES)    /* 73728 -> 2 CTAs/SM */

#define BANDLO 0xAA00u                 /* key of cos 0.046875 */
#define BANDTOP 0xAC00u                /* key of cos 0.0625   */
#define NKEY   512                     /* band keys */
#define NK4    5120                    /* extended LUT: keys BANDLO..BANDLO+5119 (cos -> 1.0 at idx 4608) */
#define BWORDS 128                     /* u32 words per row (4 byte ctrs each) */
#define KRANK  1639u                   /* rank from top: v[6553] */

// ---------------- device globals (no runtime allocation allowed) -------------
__device__ float    g_E[B*D];                    // normalized fp32 (8 MB)
__device__ __half   g_Eh[B*D];                   // normalized fp16 (4 MB)
__device__ unsigned g_mask[(size_t)B*MASKW];     // B x B bitmap (8 MB)
__device__ int      g_flags[B];
__device__ int      g_rows[B];
__device__ int      g_NR;
__device__ unsigned g_hist[(size_t)B*BWORDS];    // per-slot band histogram (4 MB)
__device__ unsigned long long g_agg[B];          // packed (cntHi<<40)|sumHi_fx
__device__ float    g_lutB[NK4];                 // exp(5*dec_key(BANDLO+i))
__device__ float    g_S[B];
__device__ float    g_pos[P];

// ---------------- helpers ----------------------------------------------------
__device__ __forceinline__ uint32_t smem_u32(const void* p) {
    uint32_t a;
    asm("{ .reg .u64 t; cvta.to.shared.u64 t, %1; cvt.u32.u64 %0, t; }" : "=r"(a) : "l"(p));
    return a;
}
__device__ __forceinline__ void cp_async16(uint32_t dst, const void* src) {
    asm volatile("cp.async.cg.shared.global [%0], [%1], 16;" :: "r"(dst), "l"(src));
}
__device__ __forceinline__ void ldsm_x4(uint32_t* r, uint32_t addr) {
    asm volatile("ldmatrix.sync.aligned.m8n8.x4.shared.b16 {%0,%1,%2,%3}, [%4];"
        : "=r"(r[0]), "=r"(r[1]), "=r"(r[2]), "=r"(r[3]) : "r"(addr));
}
__device__ __forceinline__ void mma16816(float* c, const uint32_t* a, const uint32_t* b) {
    asm volatile(
        "mma.sync.aligned.m16n8k16.row.col.f32.f16.f16.f32 "
        "{%0,%1,%2,%3}, {%4,%5,%6,%7}, {%8,%9}, {%0,%1,%2,%3};"
        : "+f"(c[0]), "+f"(c[1]), "+f"(c[2]), "+f"(c[3])
        : "r"(a[0]), "r"(a[1]), "r"(a[2]), "r"(a[3]), "r"(b[0]), "r"(b[1]));
}
// order-preserving u16 key of fp16 value
__device__ __forceinline__ unsigned short enc_key(float c) {
    unsigned short h = __half_as_ushort(__float2half_rn(c));
    return (h & 0x8000) ? (unsigned short)(~h) : (unsigned short)(h | 0x8000);
}
__device__ __forceinline__ float dec_key(unsigned k) {
    unsigned short h = (k & 0x8000u) ? (unsigned short)(k & 0x7FFFu) : (unsigned short)(~k);
    return __half2float(__ushort_as_half(h));
}
#define KEY_MASKED 0x03FFu

// ---------------- exp LUT over tracked keys ----------------------------------
__global__ void k_lut() {
    int i = blockIdx.x * 256 + threadIdx.x;
    if (i < NK4) g_lutB[i] = __expf(5.0f * dec_key(BANDLO + (unsigned)i));
}

// ---------------- normalize + fp16 + mask clear/diag + hist/agg clear --------
__global__ void k_normalize(const float* __restrict__ emb) {
    int r = blockIdx.x, t = threadIdx.x;
    __shared__ float red[256];
    float x = emb[r*D + t];
    red[t] = x * x;
    __syncthreads();
    for (int o = 128; o > 0; o >>= 1) { if (t < o) red[t] += red[t+o]; __syncthreads(); }
    float nrm = fmaxf(sqrtf(red[0]), 1e-8f);
    float e = x / nrm;
    g_E [r*D + t] = e;
    g_Eh[r*D + t] = __float2half_rn(e);
    g_mask[(size_t)r*MASKW + t] = (t == (r >> 5)) ? (1u << (r & 31)) : 0u;
    if (t < BWORDS) g_hist[(size_t)r*BWORDS + t] = 0u;
    if (t == 0) { g_agg[r] = 0ull; g_flags[r] = 0; if (r == 0) g_NR = 0; }
}

// ---------------- pairs: pos + mask bits + fused row compaction --------------
__global__ void k_pairs(const int* __restrict__ pp) {
    int w = threadIdx.x >> 5, lane = threadIdx.x & 31;
    int p = blockIdx.x * 8 + w;
    if (p >= P) return;
    int i = pp[p*2], j = pp[p*2+1];
    const float* ei = &g_E[(size_t)i*D];
    const float* ej = &g_E[(size_t)j*D];
    float s = 0.f;
    #pragma unroll
    for (int q = 0; q < 8; q++) { int d = lane + 32*q; s += ei[d] * ej[d]; }
    #pragma unroll
    for (int o = 16; o > 0; o >>= 1) s += __shfl_xor_sync(0xffffffffu, s, o);
    if (lane == 0) {
        g_pos[p] = __expf(s * 5.0f);
        atomicOr(&g_mask[(size_t)i*MASKW + (j>>5)], 1u << (j & 31));
        atomicOr(&g_mask[(size_t)j*MASKW + (i>>5)], 1u << (i & 31));
        if (atomicExch(&g_flags[i], 1) == 0) g_rows[atomicAdd(&g_NR, 1)] = i;
        if (atomicExch(&g_flags[j], 1) == 0) g_rows[atomicAdd(&g_NR, 1)] = j;
    }
}

// =================== HMMA GEMM -> band histogram + packed row aggregate ======
__device__ __forceinline__ void load_chunk(uint32_t sb, int stage, int cb, int cl,
                                           int t, const int* rows_s) {
    uint32_t stg = sb + (uint32_t)stage * STAGE_BYTES;
    #pragma unroll
    for (int i = 0; i < 4; ++i) {
        int q = t + i*256;
        int row = q >> 3, seg = q & 7;
        cp_async16(stg + row*(LDC*2) + seg*16,
                   &g_Eh[(size_t)rows_s[row]*D + cl*64 + seg*8]);
        cp_async16(stg + CHUNK_BYTES + row*(LDC*2) + seg*16,
                   &g_Eh[(size_t)(cb*128 + row)*D + cl*64 + seg*8]);
    }
    asm volatile("cp.async.commit_group;" ::: "memory");
}

__global__ void __launch_bounds__(256) k_gemm_mma() {
    int nr = g_NR;
    int rb = blockIdx.y, cb = blockIdx.x;
    if (rb * 128 >= nr) return;
    extern __shared__ __align__(16) char dsm[];
    __shared__ int rows_s[128];
    int t = threadIdx.x;
    if (t < 128) {
        int s = rb*128 + t;
        rows_s[t] = (s < nr) ? g_rows[s] : g_rows[0];
    }
    __syncthreads();
    uint32_t sb = smem_u32(dsm);

    load_chunk(sb, 0, cb, 0, t, rows_s);
    load_chunk(sb, 1, cb, 1, t, rows_s);

    int wid = t >> 5, lane = t & 31;
    int wm = wid >> 2, wn = wid & 3;
    float acc[4][4][4];
    #pragma unroll
    for (int mt = 0; mt < 4; ++mt)
        #pragma unroll
        for (int nt = 0; nt < 4; ++nt)
            #pragma unroll
            for (int q = 0; q < 4; ++q) acc[mt][nt][q] = 0.f;

    #pragma unroll
    for (int c = 0; c < 4; ++c) {
        if (c < 3) asm volatile("cp.async.wait_group 1;" ::: "memory");
        else       asm volatile("cp.async.wait_group 0;" ::: "memory");
        __syncthreads();
        uint32_t Ab = sb + (uint32_t)(c & 1) * STAGE_BYTES;
        uint32_t Bb = Ab + CHUNK_BYTES;
        #pragma unroll
        for (int kt = 0; kt < 4; ++kt) {
            int k0 = kt*16;
            uint32_t a[4][4], bfr[2][4];
            #pragma unroll
            for (int mt = 0; mt < 4; ++mt) {
                uint32_t ad = Ab + (uint32_t)(wm*64 + mt*16 + (lane & 15))*(LDC*2)
                                 + (uint32_t)(k0 + (lane >> 4)*8)*2;
                ldsm_x4(a[mt], ad);
            }
            #pragma unroll
            for (int n2 = 0; n2 < 2; ++n2) {
                int q = lane >> 3, l8 = lane & 7;
                int rowb = wn*32 + n2*16 + ((q >> 1) << 3) + l8;
                uint32_t bd = Bb + (uint32_t)rowb*(LDC*2) + (uint32_t)(k0 + (q & 1)*8)*2;
                ldsm_x4(bfr[n2], bd);
            }
            #pragma unroll
            for (int mt = 0; mt < 4; ++mt)
                #pragma unroll
                for (int nt = 0; nt < 4; ++nt) {
                    uint32_t b2[2] = { bfr[nt>>1][(nt&1)*2], bfr[nt>>1][(nt&1)*2 + 1] };
                    mma16816(acc[mt][nt], a[mt], b2);
                }
        }
        if (c + 2 < 4) {
            __syncthreads();
            load_chunk(sb, c & 1, cb, c + 2, t, rows_s);
        }
    }

    // epilogue: above-band -> LUT value into packed u64 aggregate (quad-reduced)
    //           in-band   -> byte-lane histogram RED. NO MUFU anywhere.
    int lr = lane >> 2, lc2 = (lane & 3) * 2;
    #pragma unroll
    for (int mt = 0; mt < 4; ++mt)
        #pragma unroll
        for (int h = 0; h < 2; ++h) {
            int lrow = wm*64 + mt*16 + lr + h*8;
            int sl = rb*128 + lrow;
            bool valid = (sl < nr);
            float sHi = 0.f; unsigned cHi = 0;
            if (valid) {
                int r = rows_s[lrow];
                unsigned mw = g_mask[(size_t)r*MASKW + cb*4 + wn];
                size_t hb = (size_t)sl * BWORDS;
                #pragma unroll
                for (int nt = 0; nt < 4; ++nt) {
                    int bpos = nt*8 + lc2;
                    #pragma unroll
                    for (int e2 = 0; e2 < 2; ++e2) {
                        float v = acc[mt][nt][h*2 + e2];
                        if (!((mw >> (bpos + e2)) & 1u) && v >= 0.0467f) {
                            unsigned k = enc_key(v);
                            if (k >= BANDTOP) {
                                unsigned idx = k - BANDLO;
                                if (idx > NK4-1u) idx = NK4-1u;
                                sHi += __ldg(&g_lutB[idx]);
                                cHi++;
                            } else if (k >= BANDLO) {
                                unsigned idx = k - BANDLO;
                                atomicAdd(&g_hist[hb + (idx >> 2)],
                                          1u << ((idx & 3u)*8u));
                            }
                        }
                    }
                }
            }
            unsigned long long pk =
                ((unsigned long long)cHi << 40) |
                (unsigned long long)(sHi * 1048576.0f);
            pk += __shfl_xor_sync(0xffffffffu, pk, 1);
            pk += __shfl_xor_sync(0xffffffffu, pk, 2);
            if (valid && (lane & 3) == 0 && pk)
                atomicAdd(&g_agg[sl], pk);
        }
}

// ---------------- rare exact fallback: recompute row, bisect on keys ---------
__device__ __noinline__ void row_fallback(int slot) {
    __shared__ float erow[256];
    __shared__ unsigned wr2[8];
    __shared__ float   fr2[8];
    __shared__ unsigned sflag2;
    int t = threadIdx.x, lane = t & 31, wid = t >> 5;
    int r = g_rows[slot];
    erow[t] = g_E[(size_t)r*D + t];
    __syncthreads();
    const unsigned* mrow = &g_mask[(size_t)r*MASKW];
    unsigned short keys[32];
    for (int q = 0; q < 32; ++q) {
        int c = t*32 + q;
        const float* ec = &g_E[(size_t)c*D];
        float s = 0.f;
        for (int d = 0; d < 256; ++d) s = fmaf(erow[d], ec[d], s);
        bool m = (mrow[c>>5] >> (c & 31)) & 1u;
        keys[q] = m ? (unsigned short)KEY_MASKED : enc_key(s);
    }
    unsigned cur = 0u;
    for (int bit = 15; bit >= 0; --bit) {
        unsigned cand = cur | (1u << bit);
        unsigned cnt = 0;
        for (int q = 0; q < 32; ++q) cnt += (keys[q] >= cand) ? 1u : 0u;
        #pragma unroll
        for (int o = 16; o > 0; o >>= 1) cnt += __shfl_xor_sync(0xffffffffu, cnt, o);
        if (lane == 0) wr2[wid] = cnt;
        __syncthreads();
        if (t == 0) {
            unsigned tot = 0;
            #pragma unroll
            for (int i = 0; i < 8; ++i) tot += wr2[i];
            sflag2 = (tot >= KRANK) ? 1u : 0u;
        }
        __syncthreads();
        if (sflag2) cur = cand;
        __syncthreads();
    }
    float s = 0.f;
    for (int q = 0; q < 32; ++q)
        if (keys[q] >= cur) s += __expf(5.0f * dec_key(keys[q]));
    #pragma unroll
    for (int o = 16; o > 0; o >>= 1) s += __shfl_xor_sync(0xffffffffu, s, o);
    if (lane == 0) fr2[wid] = s;
    __syncthreads();
    if (t == 0) {
        float tot = 0.f;
        #pragma unroll
        for (int i = 0; i < 8; ++i) tot += fr2[i];
        g_S[r] = tot;
    }
}

// ---------------- select3: band hist + aggregate -> exact rank + S -----------
__global__ void __launch_bounds__(256) k_select3() {
    __shared__ unsigned srev[128];
    __shared__ float fred[8];
    __shared__ int sKst, sMode;
    __shared__ unsigned sCntHi;
    __shared__ float sSumHi;
    int slot = blockIdx.x;
    if (slot >= g_NR) return;
    int t = threadIdx.x, lane = t & 31, wid = t >> 5;
    if (t == 0) {
        unsigned long long pk = g_agg[slot];
        sCntHi = (unsigned)(pk >> 40);
        sSumHi = (float)((double)(pk & ((1ull << 40) - 1ull)) * (1.0/1048576.0));
        sMode = 0; sKst = 0;
    }
    unsigned w = 0, ct = 0;
    if (t < 128) {
        w = g_hist[(size_t)slot*BWORDS + t];
        ct = __dp4a(w, 0x01010101u, 0u);
        srev[127 - t] = ct;
    }
    __syncthreads();
    #pragma unroll
    for (int o = 1; o < 128; o <<= 1) {
        unsigned v = (t < 128 && t >= o) ? srev[t - o] : 0u;
        __syncthreads();
        if (t < 128) srev[t] += v;
        __syncthreads();
    }
    unsigned cntHi = sCntHi;
    if (t < 128) {
        unsigned cge  = cntHi + srev[127 - t];
        unsigned cge1 = cntHi + ((t < 127) ? srev[126 - t] : 0u);
        if (t == 0) {
            if (cntHi >= KRANK) sMode = 1;
            if (cntHi + srev[127] < KRANK) sMode = 1;
        }
        if (cge >= KRANK && cge1 < KRANK) {
            unsigned run = cge1;
            int kst = 4*t;
            #pragma unroll
            for (int b = 3; b >= 0; --b) {
                run += (w >> (b*8)) & 255u;
                if (run >= KRANK) { kst = 4*t + b; break; }
            }
            sKst = kst;
        }
    }
    __syncthreads();
    if (sMode) { row_fallback(slot); return; }
    int kst = sKst;
    float s = 0.f;
    if (t < 128 && 4*t + 3 >= kst) {
        #pragma unroll
        for (int b = 0; b < 4; ++b) {
            int idx = 4*t + b;
            unsigned c8 = (w >> (b*8)) & 255u;
            if (idx >= kst && c8) s += (float)c8 * g_lutB[idx];
        }
    }
    #pragma unroll
    for (int o = 16; o > 0; o >>= 1) s += __shfl_xor_sync(0xffffffffu, s, o);
    if (lane == 0) fred[wid] = s;
    __syncthreads();
    if (t == 0) {
        float tot = sSumHi;
        #pragma unroll
        for (int i = 0; i < 8; ++i) tot += fred[i];
        g_S[g_rows[slot]] = tot;
    }
}

// ---------------- fused tail: bisect thr + fp32 moments + closed-form loss ---
__global__ void __launch_bounds__(256) k_tail(const int* __restrict__ pp,
                                              float* __restrict__ out) {
    __shared__ float    pv[P];
    __shared__ unsigned wredu[8];
    __shared__ double   redd[256];
    __shared__ unsigned sflag;
    __shared__ double   sm[5];
    int t = threadIdx.x, lane = t & 31, wid = t >> 5;

    unsigned pw[16];
    #pragma unroll
    for (int q = 0; q < 16; ++q) {
        float v = g_pos[t + q*256];
        pv[t + q*256] = v;
        pw[q] = __float_as_uint(v);
    }
    __syncthreads();

    const unsigned KTOP = 3277u;         // P - 819
    unsigned cur = 0u;
    for (int bit = 31; bit >= 0; --bit) {
        unsigned cand = cur | (1u << bit);
        unsigned cnt = 0;
        #pragma unroll
        for (int q = 0; q < 16; ++q) cnt += (pw[q] >= cand) ? 1u : 0u;
        #pragma unroll
        for (int o = 16; o > 0; o >>= 1) cnt += __shfl_xor_sync(0xffffffffu, cnt, o);
        if (lane == 0) wredu[wid] = cnt;
        __syncthreads();
        if (t == 0) {
            unsigned tot = 0;
            #pragma unroll
            for (int i = 0; i < 8; ++i) tot += wredu[i];
            sflag = (tot >= KTOP) ? 1u : 0u;
        }
        __syncthreads();
        if (sflag) cur = cand;
        __syncthreads();
    }
    float thr = __uint_as_float(cur);

    double m[5] = {0, 0, 0, 0, 0};
    #pragma unroll
    for (int q = 0; q < 16; ++q) {
        float v = __uint_as_float(pw[q]);
        if (v <= thr) {
            double dv = (double)v;
            m[0] += 1.0; m[1] += dv; m[2] += dv*dv; m[3] += dv*dv*dv;
            m[4] += (double)logf(v);
        }
    }
    #pragma unroll
    for (int q = 0; q < 5; ++q) {
        redd[t] = m[q]; __syncthreads();
        for (int o = 128; o > 0; o >>= 1) { if (t < o) redd[t] += redd[t+o]; __syncthreads(); }
        if (t == 0) sm[q] = redd[0];
        __syncthreads();
    }
    double kact = sm[0], P1 = sm[1], P2 = sm[2], P3 = sm[3], L = sm[4];

    double acc = 0.0;
    for (int s = t; s < 2*P; s += 256) {
        int pidx = s >> 1, side = s & 1;
        float Sf = g_S[pp[pidx*2 + side]];
        double S = (double)Sf;
        if ((double)thr / S < 0.02) {
            double inv = 1.0 / S;
            acc += kact*(double)logf(Sf) - L
                 + P1*inv - 0.5*P2*inv*inv + (1.0/3.0)*P3*inv*inv*inv;
        } else {
            for (int p = 0; p < P; ++p) {
                float pvv = pv[p];
                if (pvv <= thr) acc += (double)log1pf(Sf / pvv);
            }
        }
    }
    redd[t] = acc; __syncthreads();
    for (int o = 128; o > 0; o >>= 1) { if (t < o) redd[t] += redd[t+o]; __syncthreads(); }
    if (t == 0) out[0] = (float)(redd[0] / (2.0 * (double)P));
}

// ---------------- launch -----------------------------------------------------
extern "C" void kernel_launch(void* const* d_in, const int* in_sizes, int n_in,
                              void* d_out, int out_size) {
    const float* emb;
    const int*   pairs;
    if (in_sizes[0] == B*D) { emb = (const float*)d_in[0]; pairs = (const int*)d_in[1]; }
    else                    { emb = (const float*)d_in[1]; pairs = (const int*)d_in[0]; }
    float* out = (float*)d_out;

    cudaFuncSetAttribute(k_gemm_mma, cudaFuncAttributeMaxDynamicSharedMemorySize, GEMM_SMEM);

    k_lut      <<<(NK4+255)/256, 256>>>();             // our 1st
    k_normalize<<<B, 256>>>(emb);                      // our 2nd
    k_pairs    <<<P/8, 256>>>(pairs);                  // our 3rd
    k_gemm_mma <<<dim3(64, 64), 256, GEMM_SMEM>>>();   // our 4th -> PROFILED
    k_select3  <<<B, 256>>>();                         // our 5th
    k_tail     <<<1, 256>>>(pairs, out);               // our 6th
}

// round 16
// speedup vs baseline: 1.2168x; 1.2168x over previous
#include <cuda_runtime.h>
#include <cuda_fp16.h>
#include <math.h>
#include <stdint.h>

#define B 8192
#define D 256
#define P 4096
#define MASKW 256                      /* B/32 mask words per row */
#define LDC 72                         /* chunk smem stride in halves (64+8) */
#define CHUNK_BYTES (128*LDC*2)        /* 18432 per matrix per stage */
#define STAGE_BYTES (2*CHUNK_BYTES)    /* A+B: 36864 */
#define GEMM_SMEM   (2*STAGE_BYTES)    /* 73728 -> 2 CTAs/SM */

#define BANDLO 0xAA00u                 /* key of cos 0.046875 */
#define NK4    5120                    /* tracked keys (cos up to 1.0 at idx 4608) */
#define HWORDS 1280                    /* NK4/4 u32 words (byte counters) */
#define KRANK  1639u                   /* rank from top: v[6553] */

// ---------------- device globals (no runtime allocation allowed) -------------
__device__ float    g_E[B*D];                    // normalized fp32 (8 MB)
__device__ __half   g_Eh[B*D];                   // normalized fp16 (4 MB)
__device__ unsigned g_mask[(size_t)B*MASKW];     // B x B bitmap (8 MB)
__device__ int      g_flags[B];
__device__ int      g_rows[B];
__device__ int      g_NR;
__device__ unsigned short g_KEY[(size_t)B*B];    // u16 ordered cos keys (128 MB)
__device__ float    g_lutB[NK4];                 // exp(5*dec_key(BANDLO+i))
__device__ float    g_S[B];
__device__ float    g_pos[P];

// ---------------- helpers ----------------------------------------------------
__device__ __forceinline__ uint32_t smem_u32(const void* p) {
    uint32_t a;
    asm("{ .reg .u64 t; cvta.to.shared.u64 t, %1; cvt.u32.u64 %0, t; }" : "=r"(a) : "l"(p));
    return a;
}
__device__ __forceinline__ void cp_async16(uint32_t dst, const void* src) {
    asm volatile("cp.async.cg.shared.global [%0], [%1], 16;" :: "r"(dst), "l"(src));
}
__device__ __forceinline__ void ldsm_x4(uint32_t* r, uint32_t addr) {
    asm volatile("ldmatrix.sync.aligned.m8n8.x4.shared.b16 {%0,%1,%2,%3}, [%4];"
        : "=r"(r[0]), "=r"(r[1]), "=r"(r[2]), "=r"(r[3]) : "r"(addr));
}
__device__ __forceinline__ void mma16816(float* c, const uint32_t* a, const uint32_t* b) {
    asm volatile(
        "mma.sync.aligned.m16n8k16.row.col.f32.f16.f16.f32 "
        "{%0,%1,%2,%3}, {%4,%5,%6,%7}, {%8,%9}, {%0,%1,%2,%3};"
        : "+f"(c[0]), "+f"(c[1]), "+f"(c[2]), "+f"(c[3])
        : "r"(a[0]), "r"(a[1]), "r"(a[2]), "r"(a[3]), "r"(b[0]), "r"(b[1]));
}
// order-preserving u16 key of fp16 value
__device__ __forceinline__ unsigned short enc_key(float c) {
    unsigned short h = __half_as_ushort(__float2half_rn(c));
    return (h & 0x8000) ? (unsigned short)(~h) : (unsigned short)(h | 0x8000);
}
__device__ __forceinline__ float dec_key(unsigned k) {
    unsigned short h = (k & 0x8000u) ? (unsigned short)(k & 0x7FFFu) : (unsigned short)(~k);
    return __half2float(__ushort_as_half(h));
}
#define KEY_MASKED 0x03FFu   /* enc(-inf): below BANDLO, never histogrammed */

// ---------------- normalize + fp16 + mask clear/diag + flags + fused LUT -----
__global__ void k_normalize(const float* __restrict__ emb) {
    int r = blockIdx.x, t = threadIdx.x;
    __shared__ float red[256];
    float x = emb[r*D + t];
    red[t] = x * x;
    __syncthreads();
    for (int o = 128; o > 0; o >>= 1) { if (t < o) red[t] += red[t+o]; __syncthreads(); }
    float nrm = fmaxf(sqrtf(red[0]), 1e-8f);
    float e = x / nrm;
    g_E [r*D + t] = e;
    g_Eh[r*D + t] = __float2half_rn(e);
    g_mask[(size_t)r*MASKW + t] = (t == (r >> 5)) ? (1u << (r & 31)) : 0u;
    if (r < NK4/256) {
        int idx = r*256 + t;
        g_lutB[idx] = __expf(5.0f * dec_key(BANDLO + (unsigned)idx));
    }
    if (t == 0) { g_flags[r] = 0; if (r == 0) g_NR = 0; }
}

// ---------------- pairs: pos + mask bits + fused row compaction --------------
__global__ void k_pairs(const int* __restrict__ pp) {
    int w = threadIdx.x >> 5, lane = threadIdx.x & 31;
    int p = blockIdx.x * 8 + w;
    if (p >= P) return;
    int i = pp[p*2], j = pp[p*2+1];
    const float* ei = &g_E[(size_t)i*D];
    const float* ej = &g_E[(size_t)j*D];
    float s = 0.f;
    #pragma unroll
    for (int q = 0; q < 8; q++) { int d = lane + 32*q; s += ei[d] * ej[d]; }
    #pragma unroll
    for (int o = 16; o > 0; o >>= 1) s += __shfl_xor_sync(0xffffffffu, s, o);
    if (lane == 0) {
        g_pos[p] = __expf(s * 5.0f);
        atomicOr(&g_mask[(size_t)i*MASKW + (j>>5)], 1u << (j & 31));
        atomicOr(&g_mask[(size_t)j*MASKW + (i>>5)], 1u << (i & 31));
        if (atomicExch(&g_flags[i], 1) == 0) g_rows[atomicAdd(&g_NR, 1)] = i;
        if (atomicExch(&g_flags[j], 1) == 0) g_rows[atomicAdd(&g_NR, 1)] = j;
    }
}

// =================== HMMA GEMM -> u16 keys (R11 lean epilogue) ===============
__device__ __forceinline__ void load_chunk(uint32_t sb, int stage, int cb, int cl,
                                           int t, const int* rows_s) {
    uint32_t stg = sb + (uint32_t)stage * STAGE_BYTES;
    #pragma unroll
    for (int i = 0; i < 4; ++i) {
        int q = t + i*256;
        int row = q >> 3, seg = q & 7;
        cp_async16(stg + row*(LDC*2) + seg*16,
                   &g_Eh[(size_t)rows_s[row]*D + cl*64 + seg*8]);
        cp_async16(stg + CHUNK_BYTES + row*(LDC*2) + seg*16,
                   &g_Eh[(size_t)(cb*128 + row)*D + cl*64 + seg*8]);
    }
    asm volatile("cp.async.commit_group;" ::: "memory");
}

__global__ void __launch_bounds__(256) k_gemm_mma() {
    int nr = g_NR;
    int rb = blockIdx.y, cb = blockIdx.x;
    if (rb * 128 >= nr) return;
    extern __shared__ __align__(16) char dsm[];
    __shared__ int rows_s[128];
    int t = threadIdx.x;
    if (t < 128) {
        int s = rb*128 + t;
        rows_s[t] = (s < nr) ? g_rows[s] : g_rows[0];
    }
    __syncthreads();
    uint32_t sb = smem_u32(dsm);

    load_chunk(sb, 0, cb, 0, t, rows_s);
    load_chunk(sb, 1, cb, 1, t, rows_s);

    int wid = t >> 5, lane = t & 31;
    int wm = wid >> 2, wn = wid & 3;
    float acc[4][4][4];
    #pragma unroll
    for (int mt = 0; mt < 4; ++mt)
        #pragma unroll
        for (int nt = 0; nt < 4; ++nt)
            #pragma unroll
            for (int q = 0; q < 4; ++q) acc[mt][nt][q] = 0.f;

    #pragma unroll
    for (int c = 0; c < 4; ++c) {
        if (c < 3) asm volatile("cp.async.wait_group 1;" ::: "memory");
        else       asm volatile("cp.async.wait_group 0;" ::: "memory");
        __syncthreads();
        uint32_t Ab = sb + (uint32_t)(c & 1) * STAGE_BYTES;
        uint32_t Bb = Ab + CHUNK_BYTES;
        #pragma unroll
        for (int kt = 0; kt < 4; ++kt) {
            int k0 = kt*16;
            uint32_t a[4][4], bfr[2][4];
            #pragma unroll
            for (int mt = 0; mt < 4; ++mt) {
                uint32_t ad = Ab + (uint32_t)(wm*64 + mt*16 + (lane & 15))*(LDC*2)
                                 + (uint32_t)(k0 + (lane >> 4)*8)*2;
                ldsm_x4(a[mt], ad);
            }
            #pragma unroll
            for (int n2 = 0; n2 < 2; ++n2) {
                int q = lane >> 3, l8 = lane & 7;
                int rowb = wn*32 + n2*16 + ((q >> 1) << 3) + l8;
                uint32_t bd = Bb + (uint32_t)rowb*(LDC*2) + (uint32_t)(k0 + (q & 1)*8)*2;
                ldsm_x4(bfr[n2], bd);
            }
            #pragma unroll
            for (int mt = 0; mt < 4; ++mt)
                #pragma unroll
                for (int nt = 0; nt < 4; ++nt) {
                    uint32_t b2[2] = { bfr[nt>>1][(nt&1)*2], bfr[nt>>1][(nt&1)*2 + 1] };
                    mma16816(acc[mt][nt], a[mt], b2);
                }
        }
        if (c + 2 < 4) {
            __syncthreads();
            load_chunk(sb, c & 1, cb, c + 2, t, rows_s);
        }
    }

    // epilogue: encode keys + mask + packed u16x2 coalesced stores (lean)
    int lr = lane >> 2, lc2 = (lane & 3) * 2;
    #pragma unroll
    for (int mt = 0; mt < 4; ++mt)
        #pragma unroll
        for (int h = 0; h < 2; ++h) {
            int lrow = wm*64 + mt*16 + lr + h*8;
            int sl = rb*128 + lrow;
            if (sl >= nr) continue;
            int r = rows_s[lrow];
            unsigned mw = g_mask[(size_t)r*MASKW + cb*4 + wn];
            size_t ob = (size_t)sl*B + (size_t)(cb*128 + wn*32);
            #pragma unroll
            for (int nt = 0; nt < 4; ++nt) {
                int bpos = nt*8 + lc2;
                unsigned short k0 = ((mw >> bpos) & 1u)
                    ? (unsigned short)KEY_MASKED : enc_key(acc[mt][nt][h*2]);
                unsigned short k1 = ((mw >> (bpos+1)) & 1u)
                    ? (unsigned short)KEY_MASKED : enc_key(acc[mt][nt][h*2 + 1]);
                *(unsigned*)&g_KEY[ob + bpos] = (unsigned)k0 | ((unsigned)k1 << 16);
            }
        }
}

// ---------------- rare exact fallback: recompute row, bisect on keys ---------
__device__ __noinline__ void row_fallback(int slot) {
    __shared__ float erow[256];
    __shared__ unsigned wr2[8];
    __shared__ float   fr2[8];
    __shared__ unsigned sflag2;
    int t = threadIdx.x, lane = t & 31, wid = t >> 5;
    int r = g_rows[slot];
    erow[t] = g_E[(size_t)r*D + t];
    __syncthreads();
    const unsigned* mrow = &g_mask[(size_t)r*MASKW];
    unsigned short keys[32];
    for (int q = 0; q < 32; ++q) {
        int c = t*32 + q;
        const float* ec = &g_E[(size_t)c*D];
        float s = 0.f;
        for (int d = 0; d < 256; ++d) s = fmaf(erow[d], ec[d], s);
        bool m = (mrow[c>>5] >> (c & 31)) & 1u;
        keys[q] = m ? (unsigned short)KEY_MASKED : enc_key(s);
    }
    unsigned cur = 0u;
    for (int bit = 15; bit >= 0; --bit) {
        unsigned cand = cur | (1u << bit);
        unsigned cnt = 0;
        for (int q = 0; q < 32; ++q) cnt += (keys[q] >= cand) ? 1u : 0u;
        #pragma unroll
        for (int o = 16; o > 0; o >>= 1) cnt += __shfl_xor_sync(0xffffffffu, cnt, o);
        if (lane == 0) wr2[wid] = cnt;
        __syncthreads();
        if (t == 0) {
            unsigned tot = 0;
            #pragma unroll
            for (int i = 0; i < 8; ++i) tot += wr2[i];
            sflag2 = (tot >= KRANK) ? 1u : 0u;
        }
        __syncthreads();
        if (sflag2) cur = cand;
        __syncthreads();
    }
    float s = 0.f;
    for (int q = 0; q < 32; ++q)
        if (keys[q] >= cur) s += __expf(5.0f * dec_key(keys[q]));
    #pragma unroll
    for (int o = 16; o > 0; o >>= 1) s += __shfl_xor_sync(0xffffffffu, s, o);
    if (lane == 0) fr2[wid] = s;
    __syncthreads();
    if (t == 0) {
        float tot = 0.f;
        #pragma unroll
        for (int i = 0; i < 8; ++i) tot += fr2[i];
        g_S[r] = tot;
    }
}

// ---------------- select4: stream keys -> smem hist -> exact rank + LUT S ----
__global__ void __launch_bounds__(256) k_select4() {
    __shared__ unsigned hist[HWORDS];    // 5120 byte counters
    __shared__ unsigned srev[256];
    __shared__ float fred[8];
    __shared__ int sKst, sMode;
    int slot = blockIdx.x;
    if (slot >= g_NR) return;
    int t = threadIdx.x, lane = t & 31, wid = t >> 5;

    #pragma unroll
    for (int i = 0; i < HWORDS/256; ++i) hist[t + 256*i] = 0u;
    if (t == 0) sMode = 0;
    __syncthreads();

    // stream the 16KB key row; bin keys >= BANDLO into smem byte counters
    const uint4* src = (const uint4*)&g_KEY[(size_t)slot*B];
    #pragma unroll
    for (int q = 0; q < 4; ++q) {
        uint4 v = src[t + q*256];
        unsigned wv[4] = { v.x, v.y, v.z, v.w };
        #pragma unroll
        for (int j = 0; j < 4; ++j) {
            unsigned klo = wv[j] & 0xFFFFu, khi = wv[j] >> 16;
            if (klo >= BANDLO) {
                unsigned idx = klo - BANDLO; if (idx > NK4-1u) idx = NK4-1u;
                atomicAdd(&hist[idx >> 2], 1u << ((idx & 3u)*8u));
            }
            if (khi >= BANDLO) {
                unsigned idx = khi - BANDLO; if (idx > NK4-1u) idx = NK4-1u;
                atomicAdd(&hist[idx >> 2], 1u << ((idx & 3u)*8u));
            }
        }
    }
    __syncthreads();

    // group t = words [5t,5t+5) = keys [20t, 20t+20); suffix counts via scan
    unsigned gw[5]; unsigned ct = 0;
    #pragma unroll
    for (int j = 0; j < 5; ++j) {
        gw[j] = hist[5*t + j];
        ct = __dp4a(gw[j], 0x01010101u, ct);
    }
    srev[255 - t] = ct;
    __syncthreads();
    #pragma unroll
    for (int o = 1; o < 256; o <<= 1) {
        unsigned v = (t >= o) ? srev[t-o] : 0u; __syncthreads();
        srev[t] += v; __syncthreads();
    }
    {
        unsigned cge  = srev[255 - t];                    // keys >= 20t
        unsigned cge1 = (t < 255) ? srev[254 - t] : 0u;   // keys >= 20(t+1)
        if (t == 0 && srev[255] < KRANK) sMode = 1;       // quantile below band
        if (cge >= KRANK && cge1 < KRANK) {
            unsigned run = cge1;
            int kst = 20*t;
            #pragma unroll
            for (int j = 19; j >= 0; --j) {
                run += (gw[j>>2] >> ((j & 3)*8)) & 255u;
                if (run >= KRANK) { kst = 20*t + j; break; }
            }
            sKst = kst;
        }
    }
    __syncthreads();
    if (sMode) { row_fallback(slot); return; }

    int kst = sKst;
    float s = 0.f;
    if (20*t + 19 >= kst) {
        #pragma unroll
        for (int j = 0; j < 20; ++j) {
            int idx = 20*t + j;
            unsigned c8 = (gw[j>>2] >> ((j & 3)*8)) & 255u;
            if (idx >= kst && c8) s += (float)c8 * g_lutB[idx];
        }
    }
    #pragma unroll
    for (int o = 16; o > 0; o >>= 1) s += __shfl_xor_sync(0xffffffffu, s, o);
    if (lane == 0) fred[wid] = s;
    __syncthreads();
    if (t == 0) {
        float tot = 0.f;
        #pragma unroll
        for (int i = 0; i < 8; ++i) tot += fred[i];
        g_S[g_rows[slot]] = tot;
    }
}

// ---------------- fused tail: bisect thr + fp32 moments + closed-form loss ---
__global__ void __launch_bounds__(256) k_tail(const int* __restrict__ pp,
                                              float* __restrict__ out) {
    __shared__ float    pv[P];
    __shared__ unsigned wredu[8];
    __shared__ double   redd[256];
    __shared__ unsigned sflag;
    __shared__ double   sm[5];
    int t = threadIdx.x, lane = t & 31, wid = t >> 5;

    unsigned pw[16];
    #pragma unroll
    for (int q = 0; q < 16; ++q) {
        float v = g_pos[t + q*256];
        pv[t + q*256] = v;
        pw[q] = __float_as_uint(v);
    }
    __syncthreads();

    const unsigned KTOP = 3277u;         // P - 819
    unsigned cur = 0u;
    for (int bit = 31; bit >= 0; --bit) {
        unsigned cand = cur | (1u << bit);
        unsigned cnt = 0;
        #pragma unroll
        for (int q = 0; q < 16; ++q) cnt += (pw[q] >= cand) ? 1u : 0u;
        #pragma unroll
        for (int o = 16; o > 0; o >>= 1) cnt += __shfl_xor_sync(0xffffffffu, cnt, o);
        if (lane == 0) wredu[wid] = cnt;
        __syncthreads();
        if (t == 0) {
            unsigned tot = 0;
            #pragma unroll
            for (int i = 0; i < 8; ++i) tot += wredu[i];
            sflag = (tot >= KTOP) ? 1u : 0u;
        }
        __syncthreads();
        if (sflag) cur = cand;
        __syncthreads();
    }
    float thr = __uint_as_float(cur);

    double m[5] = {0, 0, 0, 0, 0};
    #pragma unroll
    for (int q = 0; q < 16; ++q) {
        float v = __uint_as_float(pw[q]);
        if (v <= thr) {
            double dv = (double)v;
            m[0] += 1.0; m[1] += dv; m[2] += dv*dv; m[3] += dv*dv*dv;
            m[4] += (double)logf(v);
        }
    }
    #pragma unroll
    for (int q = 0; q < 5; ++q) {
        redd[t] = m[q]; __syncthreads();
        for (int o = 128; o > 0; o >>= 1) { if (t < o) redd[t] += redd[t+o]; __syncthreads(); }
        if (t == 0) sm[q] = redd[0];
        __syncthreads();
    }
    double kact = sm[0], P1 = sm[1], P2 = sm[2], P3 = sm[3], L = sm[4];

    double acc = 0.0;
    for (int s = t; s < 2*P; s += 256) {
        int pidx = s >> 1, side = s & 1;
        float Sf = g_S[pp[pidx*2 + side]];
        double S = (double)Sf;
        if ((double)thr / S < 0.02) {
            double inv = 1.0 / S;
            acc += kact*(double)logf(Sf) - L
                 + P1*inv - 0.5*P2*inv*inv + (1.0/3.0)*P3*inv*inv*inv;
        } else {
            for (int p = 0; p < P; ++p) {
                float pvv = pv[p];
                if (pvv <= thr) acc += (double)log1pf(Sf / pvv);
            }
        }
    }
    redd[t] = acc; __syncthreads();
    for (int o = 128; o > 0; o >>= 1) { if (t < o) redd[t] += redd[t+o]; __syncthreads(); }
    if (t == 0) out[0] = (float)(redd[0] / (2.0 * (double)P));
}

// ---------------- launch -----------------------------------------------------
extern "C" void kernel_launch(void* const* d_in, const int* in_sizes, int n_in,
                              void* d_out, int out_size) {
    const float* emb;
    const int*   pairs;
    if (in_sizes[0] == B*D) { emb = (const float*)d_in[0]; pairs = (const int*)d_in[1]; }
    else                    { emb = (const float*)d_in[1]; pairs = (const int*)d_in[0]; }
    float* out = (float*)d_out;

    cudaFuncSetAttribute(k_gemm_mma, cudaFuncAttributeMaxDynamicSharedMemorySize, GEMM_SMEM);

    k_normalize<<<B, 256>>>(emb);                      // our 1st (LUT fused)
    k_pairs    <<<P/8, 256>>>(pairs);                  // our 2nd
    k_gemm_mma <<<dim3(64, 64), 256, GEMM_SMEM>>>();   // our 3rd
    k_select4  <<<B, 256>>>();                         // our 4th -> PROFILED
    k_tail     <<<1, 256>>>(pairs, out);               // our 5th
}